// round 8
// baseline (speedup 1.0000x reference)
#include <cuda_runtime.h>
#include <cuda_fp16.h>
#include <cstdint>

// AxialAttention: 512 independent attention problems of [S=512, c=64].
// B' = outer*8 + W; q/k/v/out element (B', s, c) at outer*262144 + s*512 + W*64 + c.
// attn output [B',512,512] contiguous, placed after `out` in d_out.
// R8: persistent fp16 K/V in smem + 512 threads (16 warps). Each warp: 16 rows
// x 8-key slice per 64-chunk. Register-resident scores, chunk-paired m16n8k16 PV,
// cross-warp O reduction. 8 query tiles per CTA.

#define BSTRH 72           // K/V smem row stride (halves)
#define QSTRH 72           // Q smem row stride (halves)
#define OPSTR 68           // O partial row stride (floats)
#define QROWS 32
#define NTILES 8
// float offsets
#define KS_F 0
#define VS_F 18432         // 512*72/2
#define QS_F 36864         // + 512*72/2
#define OP_F 38016         // + 32*72/2
#define RED_F 55424        // + 16*16*68
#define SMEM_FLOATS 55936
#define NEG_INF __int_as_float(0xff800000)

__device__ __forceinline__ uint32_t packh2(float a, float b) {
    __half2 h = __floats2half2_rn(a, b);
    return *reinterpret_cast<uint32_t*>(&h);
}

__device__ __forceinline__ void mma16(float* c,
        uint32_t a0, uint32_t a1, uint32_t a2, uint32_t a3,
        uint32_t b0, uint32_t b1) {
    asm volatile(
        "mma.sync.aligned.m16n8k16.row.col.f32.f16.f16.f32 "
        "{%0,%1,%2,%3},{%4,%5,%6,%7},{%8,%9},{%0,%1,%2,%3};\n"
        : "+f"(c[0]), "+f"(c[1]), "+f"(c[2]), "+f"(c[3])
        : "r"(a0), "r"(a1), "r"(a2), "r"(a3), "r"(b0), "r"(b1));
}

__device__ __forceinline__ void ldsm4(uint32_t& r0, uint32_t& r1,
                                      uint32_t& r2, uint32_t& r3, uint32_t a) {
    asm volatile("ldmatrix.sync.aligned.m8n8.x4.shared.b16 {%0,%1,%2,%3}, [%4];\n"
        : "=r"(r0), "=r"(r1), "=r"(r2), "=r"(r3) : "r"(a));
}

__device__ __forceinline__ void ldsm4t(uint32_t& r0, uint32_t& r1,
                                       uint32_t& r2, uint32_t& r3, uint32_t a) {
    asm volatile("ldmatrix.sync.aligned.m8n8.x4.trans.shared.b16 {%0,%1,%2,%3}, [%4];\n"
        : "=r"(r0), "=r"(r1), "=r"(r2), "=r"(r3) : "r"(a));
}

__global__ __launch_bounds__(512, 1)
void axial_attn_kernel(const float* __restrict__ q,
                       const float* __restrict__ k,
                       const float* __restrict__ v,
                       const int*   __restrict__ amask,
                       const float* __restrict__ hmask,
                       float* __restrict__ outp,
                       float* __restrict__ attnp)
{
    extern __shared__ float sm[];
    __half* Ks  = (__half*)(sm + KS_F);    // 512 x 72 halves
    __half* Vs  = (__half*)(sm + VS_F);    // 512 x 72 halves
    __half* Qs  = (__half*)(sm + QS_F);    // 32 x 72 halves
    float*  Op  = sm + OP_F;               // 16 warps x 16 x OPSTR
    float*  red = sm + RED_F;              // [2][8cg][32rows]

    const int tid  = threadIdx.x;
    const int w    = tid >> 5;
    const int lane = tid & 31;
    const int gid  = lane >> 2;
    const int tig  = lane & 3;
    const int rg   = w >> 3;       // row group (0/1) -> 16 rows
    const int cg   = w & 7;        // col group (0..7) -> 8 keys within 64-chunk
    const int m0   = rg * 16;
    const int cb   = cg * 8 + 2 * tig;

    const int Bp = blockIdx.y;
    const int hx = blockIdx.x;     // tile half (0/1)
    const int outer = Bp >> 3;
    const int Wd    = Bp & 7;
    const long base = (long)outer * 262144 + (long)Wd * 64;

    const float* qb = q + base;
    const float* kb = k + base;
    const float* vb = v + base;
    float* ob = outp + base;
    float* ab = attnp + (long)Bp * 262144;

    // ---- stage full K and V as fp16 (once per CTA) ----
    #pragma unroll 4
    for (int i = 0; i < 16; i++) {
        int e  = tid + 512 * i;
        int r  = e >> 4;
        int c4 = (e & 15) << 2;
        float4 tk = *(const float4*)(kb + (long)r * 512 + c4);
        float4 tv = *(const float4*)(vb + (long)r * 512 + c4);
        *(uint2*)(Ks + r * BSTRH + c4) = make_uint2(packh2(tk.x, tk.y), packh2(tk.z, tk.w));
        *(uint2*)(Vs + r * BSTRH + c4) = make_uint2(packh2(tv.x, tv.y), packh2(tv.z, tv.w));
    }

    // ldmatrix lane addressing (per-warp 8-key slice, chan blocks by lane>>3)
    const uint32_t ksA = (uint32_t)__cvta_generic_to_shared(Ks);
    const uint32_t vsA = (uint32_t)__cvta_generic_to_shared(Vs);
    const uint32_t laneoff =
        (uint32_t)((cg * 8 + (lane & 7)) * BSTRH + (lane >> 3) * 8) * 2;
    const uint32_t kaddr0 = ksA + laneoff;
    const uint32_t vaddr0 = vsA + laneoff;

    // ---- loop over 8 query tiles of 32 rows ----
    for (int t = 0; t < NTILES; t++) {
        const int q0  = (hx * NTILES + t) * QROWS;
        const int qlo = q0 + m0 + gid;
        const int qhi = qlo + 8;

        __syncthreads();   // Qs/Op free; covers staging on t=0

        // -- stage Q tile (scale 0.125, fp16) --
        {
            int r  = tid >> 4;
            int c4 = (tid & 15) << 2;
            float4 tq = *(const float4*)(qb + (long)(q0 + r) * 512 + c4);
            *(uint2*)(Qs + r * QSTRH + c4) =
                make_uint2(packh2(tq.x * 0.125f, tq.y * 0.125f),
                           packh2(tq.z * 0.125f, tq.w * 0.125f));
        }
        __syncthreads();

        // -- A fragments (Q rows m0..m0+15, k=64) --
        uint32_t A[4][4];
        #pragma unroll
        for (int ks = 0; ks < 4; ks++) {
            const __half* qr = Qs + (m0 + gid) * QSTRH + ks * 16 + 2 * tig;
            A[ks][0] = *(const uint32_t*)(qr);
            A[ks][1] = *(const uint32_t*)(qr + 8 * QSTRH);
            A[ks][2] = *(const uint32_t*)(qr + 8);
            A[ks][3] = *(const uint32_t*)(qr + 8 * QSTRH + 8);
        }

        // -- QK^T: scores in registers (16 rows x 8 keys per chunk) --
        float C[8][4];
        #pragma unroll
        for (int kc = 0; kc < 8; kc++) {
            #pragma unroll
            for (int i = 0; i < 4; i++) C[kc][i] = 0.f;
            uint32_t ka = kaddr0 + (uint32_t)kc * (64 * BSTRH * 2);
            uint32_t b0, b1, b2, b3;
            ldsm4(b0, b1, b2, b3, ka);          // chans 0-31
            mma16(C[kc], A[0][0], A[0][1], A[0][2], A[0][3], b0, b1);
            mma16(C[kc], A[1][0], A[1][1], A[1][2], A[1][3], b2, b3);
            ldsm4(b0, b1, b2, b3, ka + 64);     // chans 32-63
            mma16(C[kc], A[2][0], A[2][1], A[2][2], A[2][3], b0, b1);
            mma16(C[kc], A[3][0], A[3][1], A[3][2], A[3][3], b2, b3);
        }

        // -- mask + row max --
        const int* mloB = amask + (long)qlo * 512;
        const int* mhiB = amask + (long)qhi * 512;
        float mxl = NEG_INF, mxh = NEG_INF;
        #pragma unroll
        for (int kc = 0; kc < 8; kc++) {
            int col = kc * 64 + cb;
            int2 ml = *(const int2*)(mloB + col);
            int2 mh = *(const int2*)(mhiB + col);
            if (ml.x == 0) C[kc][0] = NEG_INF;
            if (ml.y == 0) C[kc][1] = NEG_INF;
            if (mh.x == 0) C[kc][2] = NEG_INF;
            if (mh.y == 0) C[kc][3] = NEG_INF;
            mxl = fmaxf(mxl, fmaxf(C[kc][0], C[kc][1]));
            mxh = fmaxf(mxh, fmaxf(C[kc][2], C[kc][3]));
        }
        mxl = fmaxf(mxl, __shfl_xor_sync(0xFFFFFFFFu, mxl, 1));
        mxl = fmaxf(mxl, __shfl_xor_sync(0xFFFFFFFFu, mxl, 2));
        mxh = fmaxf(mxh, __shfl_xor_sync(0xFFFFFFFFu, mxh, 1));
        mxh = fmaxf(mxh, __shfl_xor_sync(0xFFFFFFFFu, mxh, 2));
        if (tig == 0) {
            red[cg * 32 + m0 + gid]     = mxl;
            red[cg * 32 + m0 + gid + 8] = mxh;
        }
        __syncthreads();
        float gml = NEG_INF, gmh = NEG_INF;
        #pragma unroll
        for (int j = 0; j < 8; j++) {
            gml = fmaxf(gml, red[j * 32 + m0 + gid]);
            gmh = fmaxf(gmh, red[j * 32 + m0 + gid + 8]);
        }

        // -- exp + row sum --
        float sl = 0.f, sh = 0.f;
        #pragma unroll
        for (int kc = 0; kc < 8; kc++) {
            float e0 = __expf(C[kc][0] - gml);
            float e1 = __expf(C[kc][1] - gml);
            float e2 = __expf(C[kc][2] - gmh);
            float e3 = __expf(C[kc][3] - gmh);
            C[kc][0] = e0; C[kc][1] = e1; C[kc][2] = e2; C[kc][3] = e3;
            sl += e0 + e1;
            sh += e2 + e3;
        }
        sl += __shfl_xor_sync(0xFFFFFFFFu, sl, 1);
        sl += __shfl_xor_sync(0xFFFFFFFFu, sl, 2);
        sh += __shfl_xor_sync(0xFFFFFFFFu, sh, 1);
        sh += __shfl_xor_sync(0xFFFFFFFFu, sh, 2);
        __syncthreads();   // max phase reads done before sum overlay
        if (tig == 0) {
            red[256 + cg * 32 + m0 + gid]     = sl;
            red[256 + cg * 32 + m0 + gid + 8] = sh;
        }
        __syncthreads();
        float tl = 0.f, th = 0.f;
        #pragma unroll
        for (int j = 0; j < 8; j++) {
            tl += red[256 + j * 32 + m0 + gid];
            th += red[256 + j * 32 + m0 + gid + 8];
        }
        float invl = 1.0f / tl;
        float invh = 1.0f / th;

        // -- head_mask, write attn from fragments, pack P in regs --
        const float* hloB = hmask + (long)qlo * 512;
        const float* hhiB = hmask + (long)qhi * 512;
        float* aloB = ab + (long)qlo * 512;
        float* ahiB = ab + (long)qhi * 512;
        uint32_t P[8][2];
        #pragma unroll
        for (int kc = 0; kc < 8; kc++) {
            int col = kc * 64 + cb;
            float2 hl = *(const float2*)(hloB + col);
            float2 hh = *(const float2*)(hhiB + col);
            float a0 = C[kc][0] * invl * hl.x;
            float a1 = C[kc][1] * invl * hl.y;
            float a2 = C[kc][2] * invh * hh.x;
            float a3 = C[kc][3] * invh * hh.y;
            *(float2*)(aloB + col) = make_float2(a0, a1);
            *(float2*)(ahiB + col) = make_float2(a2, a3);
            P[kc][0] = packh2(a0, a1);
            P[kc][1] = packh2(a2, a3);
        }

        // -- PV: per-warp partial O (16 rows x 64 ch over this warp's 64 keys) --
        // chunk pairs -> m16n8k16 (A = P of the two chunks)
        float O[8][4];
        #pragma unroll
        for (int nt = 0; nt < 8; nt++)
            #pragma unroll
            for (int i = 0; i < 4; i++) O[nt][i] = 0.f;

        #pragma unroll
        for (int kc2 = 0; kc2 < 4; kc2++) {
            int kcA = 2 * kc2, kcB = kcA + 1;
            uint32_t vaA = vaddr0 + (uint32_t)kcA * (64 * BSTRH * 2);
            uint32_t vaB = vaddr0 + (uint32_t)kcB * (64 * BSTRH * 2);
            uint32_t a0 = P[kcA][0], a1 = P[kcA][1];
            uint32_t a2 = P[kcB][0], a3 = P[kcB][1];
            uint32_t c0, c1, c2, c3, d0, d1, d2, d3;
            ldsm4t(c0, c1, c2, c3, vaA);        // chunk A keys, chans 0-31
            ldsm4t(d0, d1, d2, d3, vaB);        // chunk B keys, chans 0-31
            mma16(O[0], a0, a1, a2, a3, c0, d0);
            mma16(O[1], a0, a1, a2, a3, c1, d1);
            mma16(O[2], a0, a1, a2, a3, c2, d2);
            mma16(O[3], a0, a1, a2, a3, c3, d3);
            ldsm4t(c0, c1, c2, c3, vaA + 64);   // chans 32-63
            ldsm4t(d0, d1, d2, d3, vaB + 64);
            mma16(O[4], a0, a1, a2, a3, c0, d0);
            mma16(O[5], a0, a1, a2, a3, c1, d1);
            mma16(O[6], a0, a1, a2, a3, c2, d2);
            mma16(O[7], a0, a1, a2, a3, c3, d3);
        }

        // -- cross-warp O reduction (8 partials per row group) --
        #pragma unroll
        for (int nt = 0; nt < 8; nt++) {
            float* p0 = Op + w * (16 * OPSTR) + gid * OPSTR + nt * 8 + 2 * tig;
            *(float2*)(p0)             = make_float2(O[nt][0], O[nt][1]);
            *(float2*)(p0 + 8 * OPSTR) = make_float2(O[nt][2], O[nt][3]);
        }
        __syncthreads();
        {
            int R   = tid >> 4;            // 0..31
            int c4  = (tid & 15) << 2;
            int wb  = (R >> 4) * 8;        // row group base warp
            int rl  = R & 15;
            float4 s = *(const float4*)(Op + (wb + 0) * (16 * OPSTR) + rl * OPSTR + c4);
            #pragma unroll
            for (int j = 1; j < 8; j++) {
                float4 u = *(const float4*)(Op + (wb + j) * (16 * OPSTR) + rl * OPSTR + c4);
                s.x += u.x; s.y += u.y; s.z += u.z; s.w += u.w;
            }
            *(float4*)(ob + (long)(q0 + R) * 512 + c4) = s;
        }
    }
}

extern "C" void kernel_launch(void* const* d_in, const int* in_sizes, int n_in,
                              void* d_out, int out_size) {
    const float* q  = (const float*)d_in[0];
    const float* k  = (const float*)d_in[1];
    const float* v  = (const float*)d_in[2];
    const int*   am = (const int*)d_in[3];
    const float* hm = (const float*)d_in[4];

    float* out  = (float*)d_out;
    float* attn = out + (long)in_sizes[0];

    size_t smem = (size_t)SMEM_FLOATS * sizeof(float);
    cudaFuncSetAttribute(axial_attn_kernel,
                         cudaFuncAttributeMaxDynamicSharedMemorySize, (int)smem);

    dim3 grid(2, 512);   // x: tile half (8 q-tiles each), y: flattened batch B'
    axial_attn_kernel<<<grid, 512, smem>>>(q, k, v, am, hm, out, attn);
}